// round 5
// baseline (speedup 1.0000x reference)
#include <cuda_runtime.h>
#include <cuda_fp16.h>

#define N_NODES 100000
#define E_EDGES 1600000
#define D 128

// ---------------- scratch (static device globals; no runtime alloc) ---------
__device__ __half g_feat_h[N_NODES * D];  // projected features, fp16 (25.6 MB)
__device__ float  g_el[N_NODES];          // src attention logits (fp32-exact)
__device__ float  g_er[N_NODES];          // dst attention logits
__device__ int    g_cnt[N_NODES];         // in-degree histogram (zeroed by agg)
__device__ int    g_off[N_NODES];         // CSR offsets
__device__ int    g_cur[N_NODES];         // scatter cursors
__device__ int2   g_sedge[E_EDGES];       // CSR slot: {src, exp-weight bits}

#define SCAN_BS 512
#define NPART ((N_NODES + SCAN_BS - 1) / SCAN_BS)   // 196
__device__ int g_part[NPART];
__device__ int g_pbase[NPART];

// ---------------- packed f32x2 helpers (sm_103a FFMA2) ----------------------
__device__ __forceinline__ unsigned long long pack2(float lo, float hi) {
    unsigned long long r;
    asm("mov.b64 %0, {%1,%2};" : "=l"(r) : "f"(lo), "f"(hi));
    return r;
}
__device__ __forceinline__ void unpack2(unsigned long long v, float& lo, float& hi) {
    asm("mov.b64 {%0,%1}, %2;" : "=f"(lo), "=f"(hi) : "l"(v));
}
__device__ __forceinline__ unsigned long long ffma2(unsigned long long a,
                                                    unsigned long long b,
                                                    unsigned long long c) {
    unsigned long long d;
    asm("fma.rn.f32x2 %0, %1, %2, %3;" : "=l"(d) : "l"(a), "l"(b), "l"(c));
    return d;
}
__device__ __forceinline__ float2 h2tof2(unsigned int u) {
    __half2 h;
    *reinterpret_cast<unsigned int*>(&h) = u;
    return __half22float2(h);
}

// ---------------- K1: hist + feat=h@W + el/er epilogue ----------------------
// 6250 blocks x 128 threads; block b: edges [b*256, b*256+256) for the
// histogram (hidden under the fma-bound mainloop) + 16 output rows.
__global__ void __launch_bounds__(128)
gemm_hist_kernel(const float* __restrict__ h, const float* __restrict__ W,
                 const float* __restrict__ attn_l, const float* __restrict__ attn_r,
                 const int* __restrict__ dst) {
    __shared__ union {
        unsigned long long hsp[D][8];   // packed pairs of rows: 8 KB
        float2             ep[16][D];   // el/er partials:       16 KB
    } sm;

    const int t = threadIdx.x;              // output column
    const int row0 = blockIdx.x * 16;

    // --- fire-and-forget histogram (REDG, no return) ---
    {
        const int e0 = blockIdx.x * 256 + t;
        atomicAdd(&g_cnt[dst[e0]], 1);
        atomicAdd(&g_cnt[dst[e0 + 128]], 1);
    }

    // --- load tile: 16 rows, pre-packed as f32x2 pairs ---
    {
        float tmp[16];
        #pragma unroll
        for (int r = 0; r < 16; r++)
            tmp[r] = h[(row0 + r) * D + t];
        #pragma unroll
        for (int j = 0; j < 8; j++)
            sm.hsp[t][j] = pack2(tmp[2*j], tmp[2*j+1]);
    }
    __syncthreads();

    unsigned long long acc2[8];
    #pragma unroll
    for (int j = 0; j < 8; j++) acc2[j] = 0ull;

    #pragma unroll 4
    for (int k = 0; k < D; k++) {
        const float wv = __ldg(&W[k * D + t]);
        const unsigned long long w2 = pack2(wv, wv);
        const ulonglong2* hk = reinterpret_cast<const ulonglong2*>(sm.hsp[k]);
        #pragma unroll
        for (int q = 0; q < 4; q++) {
            const ulonglong2 v = hk[q];         // broadcast LDS.128
            acc2[2*q]   = ffma2(v.x, w2, acc2[2*q]);
            acc2[2*q+1] = ffma2(v.y, w2, acc2[2*q+1]);
        }
    }

    // --- unpack fp32 results, store fp16 feat ---
    float f[16];
    #pragma unroll
    for (int j = 0; j < 8; j++) unpack2(acc2[j], f[2*j], f[2*j+1]);
    #pragma unroll
    for (int r = 0; r < 16; r++)
        g_feat_h[(row0 + r) * D + t] = __float2half(f[r]);

    // --- fused el/er: fp32-exact block reduction over columns ---
    const float al = __ldg(&attn_l[t]);
    const float ar = __ldg(&attn_r[t]);
    __syncthreads();                        // done reading hsp
    #pragma unroll
    for (int r = 0; r < 16; r++)
        sm.ep[r][t] = make_float2(f[r] * al, f[r] * ar);
    __syncthreads();

    const int r = t >> 3, i = t & 7;        // 8 threads per row
    float sx = 0.f, sy = 0.f;
    #pragma unroll
    for (int c = 0; c < D; c += 8) {
        const float2 p = sm.ep[r][c + i];
        sx += p.x; sy += p.y;
    }
    #pragma unroll
    for (int o = 4; o; o >>= 1) {
        sx += __shfl_down_sync(0xffffffffu, sx, o, 8);
        sy += __shfl_down_sync(0xffffffffu, sy, o, 8);
    }
    if (i == 0) { g_el[row0 + r] = sx; g_er[row0 + r] = sy; }
}

// ---------------- K2a/b/c: hierarchical exclusive scan ----------------------
__global__ void __launch_bounds__(SCAN_BS)
scanA_kernel() {
    __shared__ int sh[SCAN_BS];
    const int t = threadIdx.x;
    const int i = blockIdx.x * SCAN_BS + t;
    sh[t] = (i < N_NODES) ? g_cnt[i] : 0;
    __syncthreads();
    #pragma unroll
    for (int o = SCAN_BS / 2; o; o >>= 1) {
        if (t < o) sh[t] += sh[t + o];
        __syncthreads();
    }
    if (t == 0) g_part[blockIdx.x] = sh[0];
}

__global__ void __launch_bounds__(256)
scanB_kernel() {
    __shared__ int sh[256];
    const int t = threadIdx.x;
    const int v = (t < NPART) ? g_part[t] : 0;
    sh[t] = v;
    __syncthreads();
    for (int o = 1; o < 256; o <<= 1) {
        const int x = (t >= o) ? sh[t - o] : 0;
        __syncthreads();
        sh[t] += x;
        __syncthreads();
    }
    if (t < NPART) g_pbase[t] = sh[t] - v;       // exclusive
}

__global__ void __launch_bounds__(SCAN_BS)
scanC_kernel() {
    __shared__ int sh[SCAN_BS];
    const int t = threadIdx.x;
    const int i = blockIdx.x * SCAN_BS + t;
    const int c = (i < N_NODES) ? g_cnt[i] : 0;
    sh[t] = c;
    __syncthreads();
    for (int o = 1; o < SCAN_BS; o <<= 1) {
        const int x = (t >= o) ? sh[t - o] : 0;
        __syncthreads();
        sh[t] += x;
        __syncthreads();
    }
    if (i < N_NODES) {
        const int off = g_pbase[blockIdx.x] + sh[t] - c;   // exclusive
        g_off[i] = off;
        g_cur[i] = off;
    }
}

// ---------------- K3: fused edge score + CSR scatter ------------------------
__global__ void __launch_bounds__(256)
scatter_kernel(const int* __restrict__ src, const int* __restrict__ dst) {
    const int e = blockIdx.x * blockDim.x + threadIdx.x;
    if (e >= E_EDGES) return;
    const int s = src[e];
    const int d = dst[e];
    float x = g_el[s] + g_er[d];
    x = (x > 0.f) ? x : 0.2f * x;            // leaky relu
    const float ex = __expf(x);              // |x| small: no max-shift needed
    const int idx = atomicAdd(&g_cur[d], 1);
    g_sedge[idx] = make_int2(s, __float_as_int(ex));
}

// ---------------- K4: aggregation — warp per destination node ---------------
__global__ void __launch_bounds__(256)
agg_kernel(float* __restrict__ out) {
    const int warp = (blockIdx.x * blockDim.x + threadIdx.x) >> 5;
    const int lane = threadIdx.x & 31;
    if (warp >= N_NODES) return;

    const int beg = g_off[warp];
    const int cnt = g_cnt[warp];
    const int end = beg + cnt;
    if (lane == 0) g_cnt[warp] = 0;          // restore invariant for next run

    const uint2* __restrict__ featv = reinterpret_cast<const uint2*>(g_feat_h);

    float4 acc = make_float4(0.f, 0.f, 0.f, 0.f);
    float den = 0.f;
    int j = beg;
    for (; j + 2 <= end; j += 2) {
        const int2 p0 = g_sedge[j];
        const int2 p1 = g_sedge[j + 1];
        const uint2 v0 = __ldg(&featv[p0.x * 32 + lane]);
        const uint2 v1 = __ldg(&featv[p1.x * 32 + lane]);
        const float w0 = __int_as_float(p0.y);
        const float w1 = __int_as_float(p1.y);
        den += w0 + w1;
        const float2 a0 = h2tof2(v0.x), b0 = h2tof2(v0.y);
        const float2 a1 = h2tof2(v1.x), b1 = h2tof2(v1.y);
        acc.x = fmaf(w0, a0.x, acc.x); acc.y = fmaf(w0, a0.y, acc.y);
        acc.z = fmaf(w0, b0.x, acc.z); acc.w = fmaf(w0, b0.y, acc.w);
        acc.x = fmaf(w1, a1.x, acc.x); acc.y = fmaf(w1, a1.y, acc.y);
        acc.z = fmaf(w1, b1.x, acc.z); acc.w = fmaf(w1, b1.y, acc.w);
    }
    if (j < end) {
        const int2 p = g_sedge[j];
        const uint2 v = __ldg(&featv[p.x * 32 + lane]);
        const float w = __int_as_float(p.y);
        den += w;
        const float2 a = h2tof2(v.x), b = h2tof2(v.y);
        acc.x = fmaf(w, a.x, acc.x); acc.y = fmaf(w, a.y, acc.y);
        acc.z = fmaf(w, b.x, acc.z); acc.w = fmaf(w, b.y, acc.w);
    }
    const float inv = 1.f / fmaxf(den, 1e-9f);
    acc.x *= inv; acc.y *= inv; acc.z *= inv; acc.w *= inv;
    reinterpret_cast<float4*>(out)[warp * 32 + lane] = acc;
}

// ---------------- launch ----------------------------------------------------
extern "C" void kernel_launch(void* const* d_in, const int* in_sizes, int n_in,
                              void* d_out, int out_size) {
    const float* h      = (const float*)d_in[0];
    const int*   src    = (const int*)  d_in[1];
    const int*   dst    = (const int*)  d_in[2];
    const float* W      = (const float*)d_in[3];
    const float* attn_l = (const float*)d_in[4];
    const float* attn_r = (const float*)d_in[5];
    float* out = (float*)d_out;

    gemm_hist_kernel<<<N_NODES / 16, 128>>>(h, W, attn_l, attn_r, dst);
    scanA_kernel    <<<NPART, SCAN_BS>>>();
    scanB_kernel    <<<1, 256>>>();
    scanC_kernel    <<<NPART, SCAN_BS>>>();
    scatter_kernel  <<<(E_EDGES + 255) / 256, 256>>>(src, dst);
    agg_kernel      <<<(N_NODES * 32 + 255) / 256, 256>>>(out);
}

// round 6
// speedup vs baseline: 1.4358x; 1.4358x over previous
#include <cuda_runtime.h>
#include <cuda_fp16.h>

#define N_NODES 100000
#define E_EDGES 1600000
#define D 128

// ---------------- scratch (static device globals; no runtime alloc) ---------
__device__ float  g_feat[N_NODES * D];    // projected features fp32 (51.2 MB)
__device__ __half g_feat_h[N_NODES * D];  // projected features fp16 (25.6 MB)
__device__ float  g_el[N_NODES];          // src attention logits
__device__ float  g_er[N_NODES];          // dst attention logits
__device__ int    g_cnt[N_NODES];         // in-degree histogram
__device__ int    g_off[N_NODES];         // CSR offsets
__device__ int    g_cur[N_NODES];         // scatter cursors
__device__ int2   g_sedge[E_EDGES];       // CSR slot: {src, exp-weight bits}

#define SCAN_BS 512
#define NPART ((N_NODES + SCAN_BS - 1) / SCAN_BS)   // 196
__device__ int g_part[NPART];
__device__ int g_pbase[NPART];

// ---------------- packed f32x2 helpers (sm_103a FFMA2) ----------------------
__device__ __forceinline__ unsigned long long pack2(float lo, float hi) {
    unsigned long long r;
    asm("mov.b64 %0, {%1,%2};" : "=l"(r) : "f"(lo), "f"(hi));
    return r;
}
__device__ __forceinline__ void unpack2(unsigned long long v, float& lo, float& hi) {
    asm("mov.b64 {%0,%1}, %2;" : "=f"(lo), "=f"(hi) : "l"(v));
}
__device__ __forceinline__ unsigned long long ffma2(unsigned long long a,
                                                    unsigned long long b,
                                                    unsigned long long c) {
    unsigned long long d;
    asm("fma.rn.f32x2 %0, %1, %2, %3;" : "=l"(d) : "l"(a), "l"(b), "l"(c));
    return d;
}
__device__ __forceinline__ float2 h2tof2(unsigned int u) {
    __half2 h;
    *reinterpret_cast<unsigned int*>(&h) = u;
    return __half22float2(h);
}

// ---------------- K1: feat = h @ W  (16 rows/block, packed FFMA2) -----------
// Identical to the 230us R4 GEMM, plus an fp16 secondary store of the result.
__global__ void __launch_bounds__(128)
gemm_kernel(const float* __restrict__ h, const float* __restrict__ W) {
    __shared__ float4 hs4[D][4];
    const int t = threadIdx.x;              // output column
    const int row0 = blockIdx.x * 16;

    {
        float tmp[16];
        #pragma unroll
        for (int r = 0; r < 16; r++)
            tmp[r] = h[(row0 + r) * D + t];
        #pragma unroll
        for (int q = 0; q < 4; q++)
            hs4[t][q] = make_float4(tmp[4*q], tmp[4*q+1], tmp[4*q+2], tmp[4*q+3]);
    }
    __syncthreads();

    unsigned long long acc2[8];
    #pragma unroll
    for (int j = 0; j < 8; j++) acc2[j] = 0ull;

    #pragma unroll 4
    for (int k = 0; k < D; k++) {
        const float wv = __ldg(&W[k * D + t]);
        const unsigned long long w2 = pack2(wv, wv);
        #pragma unroll
        for (int q = 0; q < 4; q++) {
            const float4 v = hs4[k][q];
            acc2[2*q]   = ffma2(pack2(v.x, v.y), w2, acc2[2*q]);
            acc2[2*q+1] = ffma2(pack2(v.z, v.w), w2, acc2[2*q+1]);
        }
    }

    #pragma unroll
    for (int j = 0; j < 8; j++) {
        float lo, hi;
        unpack2(acc2[j], lo, hi);
        g_feat[(row0 + 2*j)     * D + t] = lo;
        g_feat[(row0 + 2*j + 1) * D + t] = hi;
        g_feat_h[(row0 + 2*j)     * D + t] = __float2half(lo);
        g_feat_h[(row0 + 2*j + 1) * D + t] = __float2half(hi);
    }
}

// ---------------- K2: el/er = feat @ attn_{l,r}  (warp per node, fp32) ------
__global__ void __launch_bounds__(256)
elr_kernel(const float* __restrict__ attn_l, const float* __restrict__ attn_r) {
    const int warp = (blockIdx.x * blockDim.x + threadIdx.x) >> 5;
    const int lane = threadIdx.x & 31;
    if (warp >= N_NODES) return;

    const float4 f  = reinterpret_cast<const float4*>(g_feat)[warp * 32 + lane];
    const float4 al = reinterpret_cast<const float4*>(attn_l)[lane];
    const float4 ar = reinterpret_cast<const float4*>(attn_r)[lane];
    float sl = f.x * al.x + f.y * al.y + f.z * al.z + f.w * al.w;
    float sr = f.x * ar.x + f.y * ar.y + f.z * ar.z + f.w * ar.w;
    #pragma unroll
    for (int o = 16; o; o >>= 1) {
        sl += __shfl_down_sync(0xffffffffu, sl, o);
        sr += __shfl_down_sync(0xffffffffu, sr, o);
    }
    if (lane == 0) { g_el[warp] = sl; g_er[warp] = sr; }
}

// ---------------- K3: zero histogram ----------------------------------------
__global__ void __launch_bounds__(256)
init_kernel() {
    const int i = blockIdx.x * blockDim.x + threadIdx.x;
    if (i < N_NODES) g_cnt[i] = 0;
}

// ---------------- K4: in-degree histogram -----------------------------------
__global__ void __launch_bounds__(256)
hist_kernel(const int* __restrict__ dst) {
    const int e = blockIdx.x * blockDim.x + threadIdx.x;
    if (e < E_EDGES) atomicAdd(&g_cnt[dst[e]], 1);
}

// ---------------- K5a/b/c: hierarchical exclusive scan ----------------------
__global__ void __launch_bounds__(SCAN_BS)
scanA_kernel() {
    __shared__ int sh[SCAN_BS];
    const int t = threadIdx.x;
    const int i = blockIdx.x * SCAN_BS + t;
    sh[t] = (i < N_NODES) ? g_cnt[i] : 0;
    __syncthreads();
    #pragma unroll
    for (int o = SCAN_BS / 2; o; o >>= 1) {
        if (t < o) sh[t] += sh[t + o];
        __syncthreads();
    }
    if (t == 0) g_part[blockIdx.x] = sh[0];
}

__global__ void __launch_bounds__(256)
scanB_kernel() {
    __shared__ int sh[256];
    const int t = threadIdx.x;
    const int v = (t < NPART) ? g_part[t] : 0;
    sh[t] = v;
    __syncthreads();
    for (int o = 1; o < 256; o <<= 1) {
        const int x = (t >= o) ? sh[t - o] : 0;
        __syncthreads();
        sh[t] += x;
        __syncthreads();
    }
    if (t < NPART) g_pbase[t] = sh[t] - v;       // exclusive
}

__global__ void __launch_bounds__(SCAN_BS)
scanC_kernel() {
    __shared__ int sh[SCAN_BS];
    const int t = threadIdx.x;
    const int i = blockIdx.x * SCAN_BS + t;
    const int c = (i < N_NODES) ? g_cnt[i] : 0;
    sh[t] = c;
    __syncthreads();
    for (int o = 1; o < SCAN_BS; o <<= 1) {
        const int x = (t >= o) ? sh[t - o] : 0;
        __syncthreads();
        sh[t] += x;
        __syncthreads();
    }
    if (i < N_NODES) {
        const int off = g_pbase[blockIdx.x] + sh[t] - c;   // exclusive
        g_off[i] = off;
        g_cur[i] = off;
    }
}

// ---------------- K6: fused edge score + CSR scatter ------------------------
__global__ void __launch_bounds__(256)
scatter_kernel(const int* __restrict__ src, const int* __restrict__ dst) {
    const int e = blockIdx.x * blockDim.x + threadIdx.x;
    if (e >= E_EDGES) return;
    const int s = src[e];
    const int d = dst[e];
    float x = g_el[s] + g_er[d];
    x = (x > 0.f) ? x : 0.2f * x;            // leaky relu
    const float ex = __expf(x);              // |x| small: no max-shift needed
    const int idx = atomicAdd(&g_cur[d], 1);
    g_sedge[idx] = make_int2(s, __float_as_int(ex));
}

// ---------------- K7: aggregation — warp per node, fp16 gather --------------
__global__ void __launch_bounds__(256)
agg_kernel(float* __restrict__ out) {
    const int warp = (blockIdx.x * blockDim.x + threadIdx.x) >> 5;
    const int lane = threadIdx.x & 31;
    if (warp >= N_NODES) return;

    const int beg = g_off[warp];
    const int end = beg + g_cnt[warp];

    const uint2* __restrict__ featv = reinterpret_cast<const uint2*>(g_feat_h);

    float4 acc = make_float4(0.f, 0.f, 0.f, 0.f);
    float den = 0.f;
    int j = beg;
    for (; j + 2 <= end; j += 2) {
        const int2 p0 = g_sedge[j];
        const int2 p1 = g_sedge[j + 1];
        const uint2 v0 = __ldg(&featv[p0.x * 32 + lane]);
        const uint2 v1 = __ldg(&featv[p1.x * 32 + lane]);
        const float w0 = __int_as_float(p0.y);
        const float w1 = __int_as_float(p1.y);
        den += w0 + w1;
        const float2 a0 = h2tof2(v0.x), b0 = h2tof2(v0.y);
        const float2 a1 = h2tof2(v1.x), b1 = h2tof2(v1.y);
        acc.x = fmaf(w0, a0.x, acc.x); acc.y = fmaf(w0, a0.y, acc.y);
        acc.z = fmaf(w0, b0.x, acc.z); acc.w = fmaf(w0, b0.y, acc.w);
        acc.x = fmaf(w1, a1.x, acc.x); acc.y = fmaf(w1, a1.y, acc.y);
        acc.z = fmaf(w1, b1.x, acc.z); acc.w = fmaf(w1, b1.y, acc.w);
    }
    if (j < end) {
        const int2 p = g_sedge[j];
        const uint2 v = __ldg(&featv[p.x * 32 + lane]);
        const float w = __int_as_float(p.y);
        den += w;
        const float2 a = h2tof2(v.x), b = h2tof2(v.y);
        acc.x = fmaf(w, a.x, acc.x); acc.y = fmaf(w, a.y, acc.y);
        acc.z = fmaf(w, b.x, acc.z); acc.w = fmaf(w, b.y, acc.w);
    }
    const float inv = 1.f / fmaxf(den, 1e-9f);
    acc.x *= inv; acc.y *= inv; acc.z *= inv; acc.w *= inv;
    reinterpret_cast<float4*>(out)[warp * 32 + lane] = acc;
}

// ---------------- launch ----------------------------------------------------
extern "C" void kernel_launch(void* const* d_in, const int* in_sizes, int n_in,
                              void* d_out, int out_size) {
    const float* h      = (const float*)d_in[0];
    const int*   src    = (const int*)  d_in[1];
    const int*   dst    = (const int*)  d_in[2];
    const float* W      = (const float*)d_in[3];
    const float* attn_l = (const float*)d_in[4];
    const float* attn_r = (const float*)d_in[5];
    float* out = (float*)d_out;

    init_kernel   <<<(N_NODES + 255) / 256, 256>>>();
    gemm_kernel   <<<N_NODES / 16, 128>>>(h, W);
    elr_kernel    <<<(N_NODES * 32 + 255) / 256, 256>>>(attn_l, attn_r);
    hist_kernel   <<<(E_EDGES + 255) / 256, 256>>>(dst);
    scanA_kernel  <<<NPART, SCAN_BS>>>();
    scanB_kernel  <<<1, 256>>>();
    scanC_kernel  <<<NPART, SCAN_BS>>>();
    scatter_kernel<<<(E_EDGES + 255) / 256, 256>>>(src, dst);
    agg_kernel    <<<(N_NODES * 32 + 255) / 256, 256>>>(out);
}